// round 10
// baseline (speedup 1.0000x reference)
#include <cuda_runtime.h>
#include <cstdint>

// Per-row mode of x[N, 64], values exactly {0..7}.
//
// R7: same 8-rows/warp structure as R6, but loads switch to Blackwell
// 256-bit vector loads (ld.global.nc.v8.f32). Lane c (0..3) of each 4-lane
// row group reads 32B chunk c and chunk c+4 of its row:
//   warp load 0 -> chunks 0..3 of 8 rows = 8 COMPLETE 128B lines
//   warp load 1 -> chunks 4..7 of 8 rows = 8 COMPLETE 128B lines
// (R6's LDG.128 pattern touched 8 half-lines per instruction.)
// Histogram machinery unchanged: FFMA magic bin + funnelshift-wrap + IADD
// into 4-bit nibble fields (2 accumulators x 8 elems, field max 8 <= 15),
// byte-split to even/odd-bin counters (4-lane reduced max 64 < 256),
// 2-level butterfly, SIMD argmax with ascending tie-break (torch.mode).

static constexpr int K = 64;

__global__ __launch_bounds__(256) void mode_rows_kernel(
    const float* __restrict__ x, float* __restrict__ out, int nrows)
{
    const int warp_id = (blockIdx.x * blockDim.x + threadIdx.x) >> 5;
    const int lane    = threadIdx.x & 31;
    const int r       = lane >> 2;   // row within warp's group of 8
    const int c       = lane & 3;    // 32B-chunk slot (0..3)

    const int row = warp_id * 8 + r;
    if (row >= nrows) return;

    // Row = 64 floats. Thread reads floats [8c..8c+7] and [8c+32..8c+39].
    const float* p = x + ((size_t)row << 6) + (c << 3);

    float a0,a1,a2,a3,a4,a5,a6,a7;      // chunk c      (line 0 of row)
    float b0,b1,b2,b3,b4,b5,b6,b7;      // chunk c+4    (line 1 of row)
    asm volatile("ld.global.nc.v8.f32 {%0,%1,%2,%3,%4,%5,%6,%7}, [%8];"
        : "=f"(a0),"=f"(a1),"=f"(a2),"=f"(a3),
          "=f"(a4),"=f"(a5),"=f"(a6),"=f"(a7)
        : "l"(p));
    asm volatile("ld.global.nc.v8.f32 {%0,%1,%2,%3,%4,%5,%6,%7}, [%8];"
        : "=f"(b0),"=f"(b1),"=f"(b2),"=f"(b3),
          "=f"(b4),"=f"(b5),"=f"(b6),"=f"(b7)
        : "l"(p + 32));

    const float MAGIC = 8388608.0f;  // 2^23; bits = 0x4B000000 | 4*bin (exact)
    unsigned n0 = 0, n1 = 0;
    n0 += __funnelshift_l(0u, 1u, __float_as_uint(fmaf(a0, 4.0f, MAGIC)));
    n0 += __funnelshift_l(0u, 1u, __float_as_uint(fmaf(a1, 4.0f, MAGIC)));
    n0 += __funnelshift_l(0u, 1u, __float_as_uint(fmaf(a2, 4.0f, MAGIC)));
    n0 += __funnelshift_l(0u, 1u, __float_as_uint(fmaf(a3, 4.0f, MAGIC)));
    n0 += __funnelshift_l(0u, 1u, __float_as_uint(fmaf(a4, 4.0f, MAGIC)));
    n0 += __funnelshift_l(0u, 1u, __float_as_uint(fmaf(a5, 4.0f, MAGIC)));
    n0 += __funnelshift_l(0u, 1u, __float_as_uint(fmaf(a6, 4.0f, MAGIC)));
    n0 += __funnelshift_l(0u, 1u, __float_as_uint(fmaf(a7, 4.0f, MAGIC)));
    n1 += __funnelshift_l(0u, 1u, __float_as_uint(fmaf(b0, 4.0f, MAGIC)));
    n1 += __funnelshift_l(0u, 1u, __float_as_uint(fmaf(b1, 4.0f, MAGIC)));
    n1 += __funnelshift_l(0u, 1u, __float_as_uint(fmaf(b2, 4.0f, MAGIC)));
    n1 += __funnelshift_l(0u, 1u, __float_as_uint(fmaf(b3, 4.0f, MAGIC)));
    n1 += __funnelshift_l(0u, 1u, __float_as_uint(fmaf(b4, 4.0f, MAGIC)));
    n1 += __funnelshift_l(0u, 1u, __float_as_uint(fmaf(b5, 4.0f, MAGIC)));
    n1 += __funnelshift_l(0u, 1u, __float_as_uint(fmaf(b6, 4.0f, MAGIC)));
    n1 += __funnelshift_l(0u, 1u, __float_as_uint(fmaf(b7, 4.0f, MAGIC)));

    // Nibble fields -> byte fields. A: bins {0,2,4,6}, B: bins {1,3,5,7}.
    // Per-thread field max 16; after 4-lane reduction max 64 < 256.
    unsigned A = (n0 & 0x0F0F0F0Fu) + (n1 & 0x0F0F0F0Fu);
    unsigned B = ((n0 >> 4) & 0x0F0F0F0Fu) + ((n1 >> 4) & 0x0F0F0F0Fu);

    // Butterfly reduce within each 4-lane group (masks 1,2 stay in-group).
    #pragma unroll
    for (int m = 1; m <= 2; m <<= 1) {
        A += __shfl_xor_sync(0xFFFFFFFFu, A, m);
        B += __shfl_xor_sync(0xFFFFFFFFu, B, m);
    }

    // Lanes with c==0 hold the full 8-bin histogram for their row.
    if (c == 0) {
        unsigned m = __vmaxu4(A, B);
        m = __vmaxu4(m, m >> 16);
        m = __vmaxu4(m, m >> 8);
        const unsigned maxc = m & 0xFFu;
        const unsigned bc = maxc * 0x01010101u;
        const unsigned eA = __vcmpeq4(A, bc);   // 0xFF per byte == maxc
        const unsigned eB = __vcmpeq4(B, bc);
        const int pA = __ffs(eA);               // lowest matching even bin
        const int pB = __ffs(eB);               // lowest matching odd bin
        const int binA = pA ? (((pA - 1) >> 3) << 1)       : 8;
        const int binB = pB ? ((((pB - 1) >> 3) << 1) | 1) : 8;
        out[row] = (float)min(binA, binB);
    }
}

extern "C" void kernel_launch(void* const* d_in, const int* in_sizes, int n_in,
                              void* d_out, int out_size)
{
    const float* x  = (const float*)d_in[0];
    float* out      = (float*)d_out;
    const int nrows = in_sizes[0] / K;                // 1048576

    const int warps_needed = (nrows + 7) / 8;         // 8 rows per warp
    const int blocks       = (warps_needed + 7) / 8;  // 8 warps per block
    mode_rows_kernel<<<blocks, 256>>>(x, out, nrows);
}

// round 12
// speedup vs baseline: 1.0795x; 1.0795x over previous
#include <cuda_runtime.h>
#include <cstdint>

// Per-row mode of x[N, 64], values exactly {0..7}.
//
// R10: 8 rows/warp with FULL-LINE loads. Thread (r=lane>>3, c=lane&7) owns
// rows base+r and base+r+4. Its 4 LDG.128:
//   L0: row r,   float4 c    -> warp instr covers line 0 of rows base..base+3
//   L1: row r,   float4 c+8  -> line 1 of rows base..base+3
//   L2: row r+4, float4 c    -> line 0 of rows base+4..base+7
//   L3: row r+4, float4 c+8  -> line 1 of rows base+4..base+7
// Every warp load instruction = 4 COMPLETE 128B lines (4 L1tex wavefronts,
// vs 8 half-lines in R6) -- halves L1tex wavefront pressure at equal DRAM
// bytes. Two per-thread histograms (one per owned row):
//   FFMA magic (v*4 + 2^23 -> low bits = 4*bin, exact) + funnelshift-wrap
//   + IADD into 8x4-bit nibble fields (8 elems/accum, max 8 <= 15).
// Byte-split to even/odd-bin counters, 3-level butterfly over 8-lane groups
// (field max 64 < 256), SIMD argmax with ascending tie-break (torch.mode).

static constexpr int K = 64;

__device__ __forceinline__ float hist_argmax(unsigned A, unsigned B)
{
    // A: byte counts of bins {0,2,4,6}; B: bins {1,3,5,7}.
    unsigned m = __vmaxu4(A, B);
    m = __vmaxu4(m, m >> 16);
    m = __vmaxu4(m, m >> 8);
    const unsigned bc = (m & 0xFFu) * 0x01010101u;
    const int pA = __ffs(__vcmpeq4(A, bc));       // lowest matching even bin
    const int pB = __ffs(__vcmpeq4(B, bc));       // lowest matching odd bin
    const int binA = pA ? (((pA - 1) >> 3) << 1)       : 8;
    const int binB = pB ? ((((pB - 1) >> 3) << 1) | 1) : 8;
    return (float)min(binA, binB);
}

__device__ __forceinline__ unsigned bin8(float4 u, float4 w)
{
    const float MAGIC = 8388608.0f;  // 2^23; bits = 0x4B000000 | 4*bin
    unsigned n = 0;
    n += __funnelshift_l(0u, 1u, __float_as_uint(fmaf(u.x, 4.0f, MAGIC)));
    n += __funnelshift_l(0u, 1u, __float_as_uint(fmaf(u.y, 4.0f, MAGIC)));
    n += __funnelshift_l(0u, 1u, __float_as_uint(fmaf(u.z, 4.0f, MAGIC)));
    n += __funnelshift_l(0u, 1u, __float_as_uint(fmaf(u.w, 4.0f, MAGIC)));
    n += __funnelshift_l(0u, 1u, __float_as_uint(fmaf(w.x, 4.0f, MAGIC)));
    n += __funnelshift_l(0u, 1u, __float_as_uint(fmaf(w.y, 4.0f, MAGIC)));
    n += __funnelshift_l(0u, 1u, __float_as_uint(fmaf(w.z, 4.0f, MAGIC)));
    n += __funnelshift_l(0u, 1u, __float_as_uint(fmaf(w.w, 4.0f, MAGIC)));
    return n;  // 8x 4-bit fields, max 8
}

__global__ __launch_bounds__(256) void mode_rows_kernel(
    const float4* __restrict__ x4, float* __restrict__ out, int nrows)
{
    const int warp_id = (blockIdx.x * blockDim.x + threadIdx.x) >> 5;
    const int lane    = threadIdx.x & 31;
    const int r       = lane >> 3;   // row slot within first group of 4
    const int c       = lane & 7;    // float4 column (0..7)

    const int base = warp_id * 8;
    if (base >= nrows) return;

    // Rows are 16 float4s. Thread owns rows base+r and base+r+4.
    const float4* p0 = x4 + ((size_t)(base + r)     << 4) + c;
    const float4* p1 = x4 + ((size_t)(base + r + 4) << 4) + c;
    const float4 u0 = p0[0];   // row r,   line 0
    const float4 u1 = p0[8];   // row r,   line 1
    const float4 w0 = p1[0];   // row r+4, line 0
    const float4 w1 = p1[8];   // row r+4, line 1

    const unsigned n0 = bin8(u0, u1);   // histogram, row base+r
    const unsigned n1 = bin8(w0, w1);   // histogram, row base+r+4

    // Nibble -> byte fields. Per-thread max 8; 8-lane reduced max 64 < 256.
    unsigned A0 = n0 & 0x0F0F0F0Fu, B0 = (n0 >> 4) & 0x0F0F0F0Fu;
    unsigned A1 = n1 & 0x0F0F0F0Fu, B1 = (n1 >> 4) & 0x0F0F0F0Fu;

    // Butterfly reduce within each 8-lane group (masks 1,2,4 stay in-group).
    #pragma unroll
    for (int m = 1; m <= 4; m <<= 1) {
        A0 += __shfl_xor_sync(0xFFFFFFFFu, A0, m);
        B0 += __shfl_xor_sync(0xFFFFFFFFu, B0, m);
        A1 += __shfl_xor_sync(0xFFFFFFFFu, A1, m);
        B1 += __shfl_xor_sync(0xFFFFFFFFu, B1, m);
    }

    // Lanes 0,8,16,24 hold both full histograms for their two rows.
    if (c == 0) {
        out[base + r]     = hist_argmax(A0, B0);
        out[base + r + 4] = hist_argmax(A1, B1);
    }
}

extern "C" void kernel_launch(void* const* d_in, const int* in_sizes, int n_in,
                              void* d_out, int out_size)
{
    const float4* x4 = (const float4*)d_in[0];
    float* out       = (float*)d_out;
    const int nrows  = in_sizes[0] / K;               // 1048576

    const int warps_needed = (nrows + 7) / 8;         // 8 rows per warp
    const int blocks       = (warps_needed + 7) / 8;  // 8 warps per block
    mode_rows_kernel<<<blocks, 256>>>(x4, out, nrows);
}